// round 8
// baseline (speedup 1.0000x reference)
#include <cuda_runtime.h>
#include <cuda_fp16.h>
#include <math.h>
#include <stdint.h>

#define NTOK   4096
#define DMODEL 2048
#define MWIDTH 5632
#define NEXP   8
#define RANK   16
#define ERANK  128
#define FSCALE 2.0f

typedef __half h16;

// ---------------- scratch (uint4 => 16B aligned) ----------------
__device__ uint4 g_x_ [(size_t)NTOK*DMODEL/8];                        // x fp16
__device__ uint4 g_wg_[(size_t)MWIDTH*DMODEL/8];
__device__ uint4 g_wu_[(size_t)MWIDTH*DMODEL/8];
__device__ uint4 g_wd_[(size_t)MWIDTH*DMODEL/8];
__device__ uint4 g_h_ [(size_t)NTOK*MWIDTH/8];                        // h fp16
__device__ uint4 g_cg_[NTOK*ERANK/8], g_cu_[NTOK*ERANK/8], g_cd_[NTOK*ERANK/8];
__device__ uint4 g_bg_[MWIDTH*ERANK/8], g_bu_[MWIDTH*ERANK/8];        // flat [n][128]
__device__ uint4 g_bd_[DMODEL*ERANK/8];

// ---------------- helpers ----------------
__device__ __forceinline__ uint32_t s2u(const void* p){
    return (uint32_t)__cvta_generic_to_shared(p);
}
__device__ __forceinline__ uint32_t sw128(uint32_t o){ return o ^ ((o >> 3) & 0x70u); }
__device__ __forceinline__ void cp16(uint32_t dst, const void* src){
    asm volatile("cp.async.cg.shared.global [%0], [%1], 16;" :: "r"(dst), "l"(src));
}
__device__ __forceinline__ void cp_commit(){ asm volatile("cp.async.commit_group;" ::: "memory"); }
__device__ __forceinline__ void cp_wait2(){ asm volatile("cp.async.wait_group 2;" ::: "memory"); }

#define LDM4(R, A) asm volatile( \
    "ldmatrix.sync.aligned.m8n8.x4.shared.b16 {%0,%1,%2,%3}, [%4];" \
    : "=r"((R)[0]), "=r"((R)[1]), "=r"((R)[2]), "=r"((R)[3]) : "r"(A))

#define MMA(D, A0, A1, A2, A3, B0, B1) asm volatile( \
    "mma.sync.aligned.m16n8k16.row.col.f32.f16.f16.f32 " \
    "{%0,%1,%2,%3}, {%4,%5,%6,%7}, {%8,%9}, {%0,%1,%2,%3};" \
    : "+f"((D)[0]), "+f"((D)[1]), "+f"((D)[2]), "+f"((D)[3]) \
    : "r"(A0), "r"(A1), "r"(A2), "r"(A3), "r"(B0), "r"(B1))

// ---------------- conversion kernels ----------------
__global__ void k_half(const float* __restrict__ in, h16* __restrict__ o, int n4){
    int i = blockIdx.x * blockDim.x + threadIdx.x;
    if (i >= n4) return;
    float4 v = ((const float4*)in)[i];
    __half2 p0 = __floats2half2_rn(v.x, v.y);
    __half2 p1 = __floats2half2_rn(v.z, v.w);
    uint2 u{*(uint32_t*)&p0, *(uint32_t*)&p1};
    ((uint2*)o)[i] = u;
}
__global__ void k_half3(const float* __restrict__ i0, h16* __restrict__ o0,
                        const float* __restrict__ i1, h16* __restrict__ o1,
                        const float* __restrict__ i2, h16* __restrict__ o2, int n4){
    const float* in = (blockIdx.y == 0) ? i0 : (blockIdx.y == 1) ? i1 : i2;
    h16*         o  = (blockIdx.y == 0) ? o0 : (blockIdx.y == 1) ? o1 : o2;
    int i = blockIdx.x * blockDim.x + threadIdx.x;
    if (i >= n4) return;
    float4 v = ((const float4*)in)[i];
    __half2 p0 = __floats2half2_rn(v.x, v.y);
    __half2 p1 = __floats2half2_rn(v.z, v.w);
    uint2 u{*(uint32_t*)&p0, *(uint32_t*)&p1};
    ((uint2*)o)[i] = u;
}
// Bexp [E,N,R] -> flat [N, E*R] fp16 ; blockIdx.y selects gate/up pair
__global__ void k_splitB2(const float* __restrict__ i0, h16* __restrict__ o0,
                          const float* __restrict__ i1, h16* __restrict__ o1, int N){
    const float* in = blockIdx.y ? i1 : i0;
    h16*         o  = blockIdx.y ? o1 : o0;
    int n = blockIdx.x, j = threadIdx.x;           // 128 threads
    int e = j >> 4, r = j & 15;
    o[(size_t)n * ERANK + j] = __float2half_rn(in[((size_t)e * N + n) * RANK + r]);
}
__global__ void k_splitB(const float* __restrict__ in, h16* __restrict__ o, int N){
    int n = blockIdx.x, j = threadIdx.x;
    int e = j >> 4, r = j & 15;
    o[(size_t)n * ERANK + j] = __float2half_rn(in[((size_t)e * N + n) * RANK + r]);
}

// ---------------- router ----------------
__global__ void k_router(const float* __restrict__ x,  const float* __restrict__ Wr,
                         const float* __restrict__ br, const float* __restrict__ Ag,
                         const float* __restrict__ Au,
                         float* __restrict__ out_routing, float* __restrict__ out_choice)
{
    __shared__ float xs[DMODEL];
    __shared__ float red[40];
    __shared__ float routing_s[NEXP];
    __shared__ int   amax_s;

    const int t = blockIdx.x;
    const float* xrow = x + (size_t)t * DMODEL;
    for (int i = threadIdx.x; i < DMODEL/4; i += blockDim.x)
        ((float4*)xs)[i] = ((const float4*)xrow)[i];
    __syncthreads();

    const int w = threadIdx.x >> 5, lane = threadIdx.x & 31;
    #pragma unroll
    for (int q = 0; q < 5; ++q) {
        const int o = w + 8*q;
        const float* wrow = (o < 8)  ? (Wr + o*DMODEL)
                          : (o < 24) ? (Ag + (o-8)*DMODEL)
                                     : (Au + (o-24)*DMODEL);
        float s = 0.f;
        for (int k = lane; k < DMODEL; k += 32) s = fmaf(xs[k], wrow[k], s);
        #pragma unroll
        for (int off = 16; off; off >>= 1) s += __shfl_xor_sync(0xffffffffu, s, off);
        if (lane == 0) red[o] = s;
    }
    __syncthreads();

    if (threadIdx.x == 0) {
        float lg[NEXP]; float mx = -1e30f;
        #pragma unroll
        for (int e = 0; e < NEXP; ++e){ lg[e] = red[e] + br[e]; mx = fmaxf(mx, lg[e]); }
        float sum = 0.f;
        #pragma unroll
        for (int e = 0; e < NEXP; ++e){ lg[e] = expf(lg[e]-mx); sum += lg[e]; }
        const float inv = 1.f/sum;
        int am = 0; float best = -1.f;
        #pragma unroll
        for (int e = 0; e < NEXP; ++e){
            const float r = lg[e]*inv; routing_s[e] = r;
            if (r > best){ best = r; am = e; }
        }
        amax_s = am;
    }
    __syncthreads();

    if (threadIdx.x < NEXP) {
        const float r = routing_s[threadIdx.x];
        out_routing[t*NEXP + threadIdx.x] = r;
        const float yh = (threadIdx.x == amax_s) ? 1.f : 0.f;
        out_choice[t*NEXP + threadIdx.x] = (yh - r) + r;
    }
    const int j = threadIdx.x & 127;
    const int e = j >> 4, rr = j & 15;
    if (threadIdx.x < 128)
        ((h16*)g_cg_)[(size_t)t*ERANK + j] = __float2half_rn(routing_s[e]*red[8+rr]*FSCALE);
    else
        ((h16*)g_cu_)[(size_t)t*ERANK + j] = __float2half_rn(routing_s[e]*red[24+rr]*FSCALE);
}

// ---------------- h @ Ad^T -> c_d ----------------
__global__ void k_hd(const float* __restrict__ Ad, const float* __restrict__ routing)
{
    __shared__ float hs[MWIDTH];
    __shared__ float red[RANK];
    const int t = blockIdx.x;
    const h16* hrow = (const h16*)g_h_ + (size_t)t * MWIDTH;
    for (int i = threadIdx.x; i < MWIDTH/2; i += blockDim.x){
        __half2 v = ((const __half2*)hrow)[i];
        float2 f = __half22float2(v);
        hs[2*i] = f.x; hs[2*i+1] = f.y;
    }
    __syncthreads();

    const int w = threadIdx.x >> 5, lane = threadIdx.x & 31;
    #pragma unroll
    for (int q = 0; q < 2; ++q) {
        const int r = w*2 + q;
        const float* arow = Ad + (size_t)r * MWIDTH;
        float s = 0.f;
        for (int k = lane; k < MWIDTH; k += 32) s = fmaf(hs[k], arow[k], s);
        #pragma unroll
        for (int off = 16; off; off >>= 1) s += __shfl_xor_sync(0xffffffffu, s, off);
        if (lane == 0) red[r] = s;
    }
    __syncthreads();
    if (threadIdx.x < 128) {
        const int e = threadIdx.x >> 4, rr = threadIdx.x & 15;
        ((h16*)g_cd_)[(size_t)t*ERANK + threadIdx.x]
            = __float2half_rn(routing[t*NEXP + e] * red[rr] * FSCALE);
    }
}

// ---------------- single-pass fp16 mma.sync GEMM, big tiles, 1 CTA/SM ----------------
// DUAL : BM=128 BN=128, warps 2m x 4n (warp tile 64x32 per acc set),
//        A=x, B0=Wg->accG, B1=Wu->accU (+aug cg/Bg, cu/Bu), silu(g)*u -> g_h_ (fp16)
// !DUAL: BM=256 BN=128, warps 4m x 2n (warp tile 64x64),
//        A=h, B0=Wd (+aug cd/Bd), epilogue -> fp32 out
// 4-stage cp.async pipeline: prologue loads 0..2; loop: wait_group 2 (tile kt
// landed), one barrier, issue kt+3 (overwrites stage (kt-1)%4, whose readers
// finished before this barrier), then MMAs on stage kt%4.
template<bool DUAL>
__global__ __launch_bounds__(256, 1)
void k_mma(float* __restrict__ OutP)
{
    constexpr int STAGES = 4;
    constexpr int BM     = DUAL ? 128 : 256;
    constexpr int BN     = 128;
    constexpr int PA     = BM * 128;                    // A plane bytes
    constexpr int PB     = BN * 128;                    // B plane bytes
    constexpr int NB     = DUAL ? 2 : 1;
    constexpr int STAGEB = PA + NB * PB;                // 48KB both variants
    constexpr int WNW    = DUAL ? 4 : 2;                // n-warps
    constexpr int WTN    = BN / WNW;                    // 32 / 64
    constexpr int JN     = WTN / 8;                     // 4 / 8
    constexpr int NKM    = DUAL ? (DMODEL/64) : (MWIDTH/64);  // 32 / 88
    constexpr int NT     = DUAL ? (NKM + 4) : (NKM + 2);

    extern __shared__ __align__(16) char smem[];
    const uint32_t sb = s2u(smem);
    const int tid = threadIdx.x, wid = tid >> 5, lane = tid & 31;
    const int wm = DUAL ? (wid >> 2) : (wid & 3);       // 0..1 / 0..3
    const int wn = DUAL ? (wid & 3)  : (wid >> 2);      // 0..3 / 0..1
    const int m0 = blockIdx.y * BM, n0 = blockIdx.x * BN;

    float accG[4][JN][4];
    float accU[DUAL?4:1][DUAL?JN:1][4];
    #pragma unroll
    for (int m=0;m<4;++m) for (int j=0;j<JN;++j) for (int q=0;q<4;++q) accG[m][j][q]=0.f;
    if constexpr (DUAL){
        #pragma unroll
        for (int m=0;m<4;++m) for (int j=0;j<JN;++j) for (int q=0;q<4;++q) accU[m][j][q]=0.f;
    }

    auto ldplane = [&](uint32_t dst, const h16* src, int stride, int rbase,
                       int koff, int nrows){
        for (int it = 0; it < nrows/32; ++it){
            const int id = tid + it*256;
            const int row = id >> 3, ch = id & 7;
            cp16(dst + sw128((uint32_t)(row*128 + ch*16)),
                 src + (size_t)(rbase + row)*stride + koff + ch*8);
        }
    };
    auto load_chunk = [&](int kt){
        const uint32_t st = sb + (uint32_t)(kt % STAGES) * STAGEB;
        if constexpr (DUAL){
            if (kt < NKM){
                ldplane(st,       (const h16*)g_x_,  DMODEL, m0, kt*64, BM);
                ldplane(st+PA,    (const h16*)g_wg_, DMODEL, n0, kt*64, BN);
                ldplane(st+PA+PB, (const h16*)g_wu_, DMODEL, n0, kt*64, BN);
            } else {
                const bool gsel = kt < NKM+2;
                const int ko = (kt - NKM - (gsel ? 0 : 2)) * 64;
                ldplane(st,    gsel ? (const h16*)g_cg_ : (const h16*)g_cu_, ERANK, m0, ko, BM);
                ldplane(st+PA, gsel ? (const h16*)g_bg_ : (const h16*)g_bu_, ERANK, n0, ko, BN);
            }
        } else {
            if (kt < NKM){
                ldplane(st,    (const h16*)g_h_,  MWIDTH, m0, kt*64, BM);
                ldplane(st+PA, (const h16*)g_wd_, MWIDTH, n0, kt*64, BN);
            } else {
                const int ko = (kt - NKM) * 64;
                ldplane(st,    (const h16*)g_cd_, ERANK, m0, ko, BM);
                ldplane(st+PA, (const h16*)g_bd_, ERANK, n0, ko, BN);
            }
        }
        cp_commit();
    };
    auto ldaddr = [&](uint32_t pbase, int rbase, int kb) -> uint32_t {
        const int row = rbase + (lane & 15);
        return pbase + sw128((uint32_t)(row*128 + kb + ((lane >> 4) << 4)));
    };

    load_chunk(0);
    load_chunk(1);
    load_chunk(2);

    for (int kt = 0; kt < NT; ++kt){
        // Issued: tiles 0..kt+2 (3 groups in first iter). <=2 pending => tile kt done.
        cp_wait2();
        __syncthreads();                      // stage kt visible; readers of (kt-1)%4 done
        if (kt + 3 < NT) load_chunk(kt + 3);  // overwrite (kt-1)%4; overlaps MMAs

        const uint32_t st = sb + (uint32_t)(kt % STAGES) * STAGEB;
        // mode: 0 main, 1 aug->accG, 2 aug->accU
        int mode = 0;
        if (kt >= NKM) mode = (DUAL && kt >= NKM+2) ? 2 : 1;

        #pragma unroll
        for (int ks = 0; ks < 4; ++ks){
            const int kb = ks*32;
            uint32_t a[4][4];
            #pragma unroll
            for (int mf = 0; mf < 4; ++mf)
                LDM4(a[mf], ldaddr(st, wm*64 + mf*16, kb));

            if constexpr (DUAL){
                uint32_t bb[2][4];
                #pragma unroll
                for (int g = 0; g < 2; ++g)
                    LDM4(bb[g], ldaddr(st+PA, wn*WTN + g*16, kb));
                if (mode != 2){
                    #pragma unroll
                    for (int mf = 0; mf < 4; ++mf)
                        #pragma unroll
                        for (int j = 0; j < JN; ++j)
                            MMA(accG[mf][j], a[mf][0],a[mf][1],a[mf][2],a[mf][3],
                                bb[j>>1][j&1], bb[j>>1][(j&1)+2]);
                } else {
                    #pragma unroll
                    for (int mf = 0; mf < 4; ++mf)
                        #pragma unroll
                        for (int j = 0; j < JN; ++j)
                            MMA(accU[mf][j], a[mf][0],a[mf][1],a[mf][2],a[mf][3],
                                bb[j>>1][j&1], bb[j>>1][(j&1)+2]);
                }
                if (mode == 0){
                    #pragma unroll
                    for (int g = 0; g < 2; ++g)
                        LDM4(bb[g], ldaddr(st+PA+PB, wn*WTN + g*16, kb));
                    #pragma unroll
                    for (int mf = 0; mf < 4; ++mf)
                        #pragma unroll
                        for (int j = 0; j < JN; ++j)
                            MMA(accU[mf][j], a[mf][0],a[mf][1],a[mf][2],a[mf][3],
                                bb[j>>1][j&1], bb[j>>1][(j&1)+2]);
                }
            } else {
                uint32_t bb[4][4];
                #pragma unroll
                for (int g = 0; g < 4; ++g)
                    LDM4(bb[g], ldaddr(st+PA, wn*WTN + g*16, kb));
                #pragma unroll
                for (int mf = 0; mf < 4; ++mf)
                    #pragma unroll
                    for (int j = 0; j < JN; ++j)
                        MMA(accG[mf][j], a[mf][0],a[mf][1],a[mf][2],a[mf][3],
                            bb[j>>1][j&1], bb[j>>1][(j&1)+2]);
            }
        }
    }

    // ---------------- epilogue ----------------
    #pragma unroll
    for (int mf = 0; mf < 4; ++mf){
        #pragma unroll
        for (int j = 0; j < JN; ++j){
            const int r0 = m0 + wm*64 + mf*16 + (lane >> 2);
            const int c0 = n0 + wn*WTN + j*8 + (lane & 3)*2;
            if constexpr (DUAL){
                h16* gh = (h16*)g_h_;
                float hv[4];
                #pragma unroll
                for (int q = 0; q < 4; ++q){
                    const float g = accG[mf][j][q], u = accU[mf][j][q];
                    hv[q] = g * u / (1.f + __expf(-g));
                }
                *(__half2*)(gh + (size_t)r0*MWIDTH + c0)     = __floats2half2_rn(hv[0], hv[1]);
                *(__half2*)(gh + (size_t)(r0+8)*MWIDTH + c0) = __floats2half2_rn(hv[2], hv[3]);
            } else {
                *(float2*)(OutP + (size_t)r0*DMODEL + c0)
                    = make_float2(accG[mf][j][0], accG[mf][j][1]);
                *(float2*)(OutP + (size_t)(r0+8)*DMODEL + c0)
                    = make_float2(accG[mf][j][2], accG[mf][j][3]);
            }
        }
    }
}

// ---------------------------------------------------------------------------
extern "C" void kernel_launch(void* const* d_in, const int* in_sizes, int n_in,
                              void* d_out, int out_size)
{
    const float* x  = (const float*)d_in[0];
    const float* Wr = (const float*)d_in[1];
    const float* br = (const float*)d_in[2];
    const float* Wg = (const float*)d_in[3];
    const float* Wu = (const float*)d_in[4];
    const float* Wd = (const float*)d_in[5];
    const float* Ag = (const float*)d_in[6];
    const float* Au = (const float*)d_in[7];
    const float* Ad = (const float*)d_in[8];
    const float* Bg = (const float*)d_in[9];
    const float* Bu = (const float*)d_in[10];
    const float* Bd = (const float*)d_in[11];

    float* out     = (float*)d_out;
    float* routing = out + (size_t)NTOK * DMODEL;
    float* choice  = routing + NTOK * NEXP;

    void *xp,*wg,*wu,*wd,*bg,*bu,*bd;
    cudaGetSymbolAddress(&xp, g_x_);
    cudaGetSymbolAddress(&wg, g_wg_); cudaGetSymbolAddress(&wu, g_wu_);
    cudaGetSymbolAddress(&wd, g_wd_);
    cudaGetSymbolAddress(&bg, g_bg_); cudaGetSymbolAddress(&bu, g_bu_);
    cudaGetSymbolAddress(&bd, g_bd_);

    const int n4x = NTOK*DMODEL/4, n4w = MWIDTH*DMODEL/4;
    k_half<<<(n4x+255)/256, 256>>>(x, (h16*)xp, n4x);
    k_half3<<<dim3((n4w+255)/256, 3), 256>>>(Wg, (h16*)wg, Wu, (h16*)wu, Wd, (h16*)wd, n4w);
    k_splitB2<<<dim3(MWIDTH, 2), 128>>>(Bg, (h16*)bg, Bu, (h16*)bu, MWIDTH);
    k_splitB<<<DMODEL, 128>>>(Bd, (h16*)bd, DMODEL);

    k_router<<<NTOK, 256>>>(x, Wr, br, Ag, Au, routing, choice);

    const int smem_sz = 4 * 49152;   // 196608 both variants
    cudaFuncSetAttribute(k_mma<true>,  cudaFuncAttributeMaxDynamicSharedMemorySize, smem_sz);
    cudaFuncSetAttribute(k_mma<false>, cudaFuncAttributeMaxDynamicSharedMemorySize, smem_sz);

    // DUAL: grid (MWIDTH/128=44, NTOK/128=32)
    k_mma<true><<<dim3(MWIDTH/128, NTOK/128), 256, smem_sz>>>(nullptr);
    k_hd<<<NTOK, 256>>>(Ad, routing);
    // down: grid (DMODEL/128=16, NTOK/256=16)
    k_mma<false><<<dim3(DMODEL/128, NTOK/256), 256, smem_sz>>>(out);
}

// round 9
// speedup vs baseline: 1.1404x; 1.1404x over previous
#include <cuda_runtime.h>
#include <cuda_fp16.h>
#include <math.h>
#include <stdint.h>

#define NTOK   4096
#define DMODEL 2048
#define MWIDTH 5632
#define NEXP   8
#define RANK   16
#define ERANK  128
#define FSCALE 2.0f

typedef __half h16;

// ---------------- scratch (uint4 => 16B aligned) ----------------
__device__ uint4 g_x_ [(size_t)NTOK*DMODEL/8];                        // x fp16
__device__ uint4 g_wg_[(size_t)MWIDTH*DMODEL/8];
__device__ uint4 g_wu_[(size_t)MWIDTH*DMODEL/8];
__device__ uint4 g_wd_[(size_t)MWIDTH*DMODEL/8];
__device__ uint4 g_h_ [(size_t)NTOK*MWIDTH/8];                        // h fp16
__device__ uint4 g_cg_[NTOK*ERANK/8], g_cu_[NTOK*ERANK/8], g_cd_[NTOK*ERANK/8];
__device__ uint4 g_bg_[MWIDTH*ERANK/8], g_bu_[MWIDTH*ERANK/8];        // flat [n][128]
__device__ uint4 g_bd_[DMODEL*ERANK/8];

// ---------------- helpers ----------------
__device__ __forceinline__ uint32_t s2u(const void* p){
    return (uint32_t)__cvta_generic_to_shared(p);
}
__device__ __forceinline__ uint32_t sw128(uint32_t o){ return o ^ ((o >> 3) & 0x70u); }
__device__ __forceinline__ void cp16(uint32_t dst, const void* src){
    asm volatile("cp.async.cg.shared.global [%0], [%1], 16;" :: "r"(dst), "l"(src));
}
__device__ __forceinline__ void cp_commit(){ asm volatile("cp.async.commit_group;" ::: "memory"); }
__device__ __forceinline__ void cp_wait1(){ asm volatile("cp.async.wait_group 1;" ::: "memory"); }

#define LDM4(R, A) asm volatile( \
    "ldmatrix.sync.aligned.m8n8.x4.shared.b16 {%0,%1,%2,%3}, [%4];" \
    : "=r"((R)[0]), "=r"((R)[1]), "=r"((R)[2]), "=r"((R)[3]) : "r"(A))

#define MMA(D, A0, A1, A2, A3, B0, B1) asm volatile( \
    "mma.sync.aligned.m16n8k16.row.col.f32.f16.f16.f32 " \
    "{%0,%1,%2,%3}, {%4,%5,%6,%7}, {%8,%9}, {%0,%1,%2,%3};" \
    : "+f"((D)[0]), "+f"((D)[1]), "+f"((D)[2]), "+f"((D)[3]) \
    : "r"(A0), "r"(A1), "r"(A2), "r"(A3), "r"(B0), "r"(B1))

// ---------------- fused conversion kernels ----------------
// blockIdx.y: 0=x (n4a elems), 1..3 = Wg/Wu/Wd (n4b elems)
__global__ void k_cvt(const float* __restrict__ i0, h16* __restrict__ o0, int n4a,
                      const float* __restrict__ i1, h16* __restrict__ o1,
                      const float* __restrict__ i2, h16* __restrict__ o2,
                      const float* __restrict__ i3, h16* __restrict__ o3, int n4b){
    const int y = blockIdx.y;
    const float* in = (y == 0) ? i0 : (y == 1) ? i1 : (y == 2) ? i2 : i3;
    h16*         o  = (y == 0) ? o0 : (y == 1) ? o1 : (y == 2) ? o2 : o3;
    const int n4 = (y == 0) ? n4a : n4b;
    int i = blockIdx.x * blockDim.x + threadIdx.x;
    if (i >= n4) return;
    float4 v = ((const float4*)in)[i];
    __half2 p0 = __floats2half2_rn(v.x, v.y);
    __half2 p1 = __floats2half2_rn(v.z, v.w);
    uint2 u{*(uint32_t*)&p0, *(uint32_t*)&p1};
    ((uint2*)o)[i] = u;
}
// Bexp [E,N,R] -> flat [N, E*R] fp16 ; blockIdx.y: 0=Bg, 1=Bu (N=MWIDTH), 2=Bd (N=DMODEL)
__global__ void k_bflat(const float* __restrict__ i0, h16* __restrict__ o0,
                        const float* __restrict__ i1, h16* __restrict__ o1,
                        const float* __restrict__ i2, h16* __restrict__ o2){
    const int y = blockIdx.y;
    const float* in = (y == 0) ? i0 : (y == 1) ? i1 : i2;
    h16*         o  = (y == 0) ? o0 : (y == 1) ? o1 : o2;
    const int N = (y == 2) ? DMODEL : MWIDTH;
    const int n = blockIdx.x;
    if (n >= N) return;
    const int j = threadIdx.x;                 // 128 threads
    const int e = j >> 4, r = j & 15;
    o[(size_t)n * ERANK + j] = __float2half_rn(in[((size_t)e * N + n) * RANK + r]);
}

// ---------------- router ----------------
__global__ void k_router(const float* __restrict__ x,  const float* __restrict__ Wr,
                         const float* __restrict__ br, const float* __restrict__ Ag,
                         const float* __restrict__ Au,
                         float* __restrict__ out_routing, float* __restrict__ out_choice)
{
    __shared__ float xs[DMODEL];
    __shared__ float red[40];
    __shared__ float routing_s[NEXP];
    __shared__ int   amax_s;

    const int t = blockIdx.x;
    const float* xrow = x + (size_t)t * DMODEL;
    for (int i = threadIdx.x; i < DMODEL/4; i += blockDim.x)
        ((float4*)xs)[i] = ((const float4*)xrow)[i];
    __syncthreads();

    const int w = threadIdx.x >> 5, lane = threadIdx.x & 31;
    #pragma unroll
    for (int q = 0; q < 5; ++q) {
        const int o = w + 8*q;
        const float* wrow = (o < 8)  ? (Wr + o*DMODEL)
                          : (o < 24) ? (Ag + (o-8)*DMODEL)
                                     : (Au + (o-24)*DMODEL);
        float s = 0.f;
        for (int k = lane; k < DMODEL; k += 32) s = fmaf(xs[k], wrow[k], s);
        #pragma unroll
        for (int off = 16; off; off >>= 1) s += __shfl_xor_sync(0xffffffffu, s, off);
        if (lane == 0) red[o] = s;
    }
    __syncthreads();

    if (threadIdx.x == 0) {
        float lg[NEXP]; float mx = -1e30f;
        #pragma unroll
        for (int e = 0; e < NEXP; ++e){ lg[e] = red[e] + br[e]; mx = fmaxf(mx, lg[e]); }
        float sum = 0.f;
        #pragma unroll
        for (int e = 0; e < NEXP; ++e){ lg[e] = expf(lg[e]-mx); sum += lg[e]; }
        const float inv = 1.f/sum;
        int am = 0; float best = -1.f;
        #pragma unroll
        for (int e = 0; e < NEXP; ++e){
            const float r = lg[e]*inv; routing_s[e] = r;
            if (r > best){ best = r; am = e; }
        }
        amax_s = am;
    }
    __syncthreads();

    if (threadIdx.x < NEXP) {
        const float r = routing_s[threadIdx.x];
        out_routing[t*NEXP + threadIdx.x] = r;
        const float yh = (threadIdx.x == amax_s) ? 1.f : 0.f;
        out_choice[t*NEXP + threadIdx.x] = (yh - r) + r;
    }
    const int j = threadIdx.x & 127;
    const int e = j >> 4, rr = j & 15;
    if (threadIdx.x < 128)
        ((h16*)g_cg_)[(size_t)t*ERANK + j] = __float2half_rn(routing_s[e]*red[8+rr]*FSCALE);
    else
        ((h16*)g_cu_)[(size_t)t*ERANK + j] = __float2half_rn(routing_s[e]*red[24+rr]*FSCALE);
}

// ---------------- h @ Ad^T -> c_d ----------------
__global__ void k_hd(const float* __restrict__ Ad, const float* __restrict__ routing)
{
    __shared__ float hs[MWIDTH];
    __shared__ float red[RANK];
    const int t = blockIdx.x;
    const h16* hrow = (const h16*)g_h_ + (size_t)t * MWIDTH;
    for (int i = threadIdx.x; i < MWIDTH/2; i += blockDim.x){
        __half2 v = ((const __half2*)hrow)[i];
        float2 f = __half22float2(v);
        hs[2*i] = f.x; hs[2*i+1] = f.y;
    }
    __syncthreads();

    const int w = threadIdx.x >> 5, lane = threadIdx.x & 31;
    #pragma unroll
    for (int q = 0; q < 2; ++q) {
        const int r = w*2 + q;
        const float* arow = Ad + (size_t)r * MWIDTH;
        float s = 0.f;
        for (int k = lane; k < MWIDTH; k += 32) s = fmaf(hs[k], arow[k], s);
        #pragma unroll
        for (int off = 16; off; off >>= 1) s += __shfl_xor_sync(0xffffffffu, s, off);
        if (lane == 0) red[r] = s;
    }
    __syncthreads();
    if (threadIdx.x < 128) {
        const int e = threadIdx.x >> 4, rr = threadIdx.x & 15;
        ((h16*)g_cd_)[(size_t)t*ERANK + threadIdx.x]
            = __float2half_rn(routing[t*NEXP + e] * red[rr] * FSCALE);
    }
}

// ---------------- single-pass fp16 mma.sync GEMM, 2 CTAs/SM (R7 config) ----------------
// Mainloop: wait_group 1 -> single __syncthreads -> issue loads(kt+2) -> MMAs.
// DUAL : BM=128 BN=64,  A=x,  B0=Wg->accG, B1=Wu->accU (+aug cg/Bg, cu/Bu),
//        epilogue silu(g)*u -> g_h_ (fp16).  Grid: x = m-blocks, y = n-blocks
//        (concurrent CTAs share the larger B working set in L2).
// !DUAL: BM=128 BN=128, A=h,  B0=Wd (+aug cd/Bd), epilogue -> fp32 out.
template<bool DUAL>
__global__ __launch_bounds__(256, 2)
void k_mma(float* __restrict__ OutP)
{
    constexpr int STAGES = 3;
    constexpr int PA     = 16384;                       // A plane: 128 rows x 128B
    constexpr int PB     = DUAL ? 8192 : 16384;         // B plane
    constexpr int STAGEB = PA + (DUAL ? 2 : 1) * PB;    // 32KB both variants
    constexpr int BN     = DUAL ? 64 : 128;
    constexpr int JN     = DUAL ? 4 : 8;                // 8-col groups per warp n-tile
    constexpr int WTN    = DUAL ? 32 : 64;
    constexpr int NKM    = DUAL ? (DMODEL/64) : (MWIDTH/64);  // 32 / 88
    constexpr int NT     = DUAL ? (NKM + 4) : (NKM + 2);

    extern __shared__ __align__(16) char smem[];
    const uint32_t sb = s2u(smem);
    const int tid = threadIdx.x, wid = tid >> 5, lane = tid & 31;
    const int wm = wid & 3, wn = wid >> 2;
    const int m0 = (DUAL ? blockIdx.x : blockIdx.y) * 128;
    const int n0 = (DUAL ? blockIdx.y : blockIdx.x) * BN;

    float accG[2][JN][4];
    float accU[DUAL?2:1][DUAL?JN:1][4];
    #pragma unroll
    for (int m=0;m<2;++m) for (int j=0;j<JN;++j) for (int q=0;q<4;++q) accG[m][j][q]=0.f;
    if constexpr (DUAL){
        #pragma unroll
        for (int m=0;m<2;++m) for (int j=0;j<JN;++j) for (int q=0;q<4;++q) accU[m][j][q]=0.f;
    }

    auto ldplane = [&](uint32_t dst, const h16* src, int stride, int rbase,
                       int koff, int nrows){
        for (int it = 0; it < nrows/32; ++it){
            const int id = tid + it*256;
            const int row = id >> 3, ch = id & 7;
            cp16(dst + sw128((uint32_t)(row*128 + ch*16)),
                 src + (size_t)(rbase + row)*stride + koff + ch*8);
        }
    };
    auto load_chunk = [&](int kt){
        const uint32_t st = sb + (uint32_t)(kt % STAGES) * STAGEB;
        if constexpr (DUAL){
            if (kt < NKM){
                ldplane(st,       (const h16*)g_x_,  DMODEL, m0, kt*64, 128);
                ldplane(st+PA,    (const h16*)g_wg_, DMODEL, n0, kt*64, 64);
                ldplane(st+PA+PB, (const h16*)g_wu_, DMODEL, n0, kt*64, 64);
            } else {
                const bool gsel = kt < NKM+2;
                const int ko = (kt - NKM - (gsel ? 0 : 2)) * 64;
                ldplane(st,    gsel ? (const h16*)g_cg_ : (const h16*)g_cu_, ERANK, m0, ko, 128);
                ldplane(st+PA, gsel ? (const h16*)g_bg_ : (const h16*)g_bu_, ERANK, n0, ko, 64);
            }
        } else {
            if (kt < NKM){
                ldplane(st,    (const h16*)g_h_,  MWIDTH, m0, kt*64, 128);
                ldplane(st+PA, (const h16*)g_wd_, MWIDTH, n0, kt*64, 128);
            } else {
                const int ko = (kt - NKM) * 64;
                ldplane(st,    (const h16*)g_cd_, ERANK, m0, ko, 128);
                ldplane(st+PA, (const h16*)g_bd_, ERANK, n0, ko, 128);
            }
        }
        cp_commit();
    };
    auto ldaddr = [&](uint32_t pbase, int rbase, int kb) -> uint32_t {
        const int row = rbase + (lane & 15);
        return pbase + sw128((uint32_t)(row*128 + kb + ((lane >> 4) << 4)));
    };

    load_chunk(0);
    load_chunk(1);

    for (int kt = 0; kt < NT; ++kt){
        // Issued so far: tiles 0..kt+1. <=1 pending  =>  tile kt complete.
        cp_wait1();
        __syncthreads();                      // stage kt visible to all warps; all
                                              // reads of stage (kt-1)%3 are done.
        if (kt + 2 < NT) load_chunk(kt + 2);  // overwrite (kt-1)%3; issue overlaps MMAs

        const uint32_t st = sb + (uint32_t)(kt % STAGES) * STAGEB;
        // mode: 0 main, 1 aug->accG, 2 aug->accU
        int mode = 0;
        if (kt >= NKM) mode = (DUAL && kt >= NKM+2) ? 2 : 1;

        #pragma unroll
        for (int ks = 0; ks < 4; ++ks){
            const int kb = ks*32;
            uint32_t a0[4], a1[4], bb[JN/2][4];
            LDM4(a0, ldaddr(st, wm*32,    kb));
            LDM4(a1, ldaddr(st, wm*32+16, kb));
            #pragma unroll
            for (int g = 0; g < JN/2; ++g)
                LDM4(bb[g], ldaddr(st+PA, wn*WTN + g*16, kb));

            if (mode != 2){
                #pragma unroll
                for (int j = 0; j < JN; ++j){
                    const uint32_t bx = bb[j>>1][j&1], by = bb[j>>1][(j&1)+2];
                    MMA(accG[0][j], a0[0],a0[1],a0[2],a0[3], bx, by);
                    MMA(accG[1][j], a1[0],a1[1],a1[2],a1[3], bx, by);
                }
            } else {
                #pragma unroll
                for (int j = 0; j < JN; ++j){
                    const uint32_t bx = bb[j>>1][j&1], by = bb[j>>1][(j&1)+2];
                    MMA(accU[0][j], a0[0],a0[1],a0[2],a0[3], bx, by);
                    MMA(accU[1][j], a1[0],a1[1],a1[2],a1[3], bx, by);
                }
            }
            if constexpr (DUAL){
                if (mode == 0){
                    #pragma unroll
                    for (int g = 0; g < JN/2; ++g)
                        LDM4(bb[g], ldaddr(st+PA+PB, wn*WTN + g*16, kb));
                    #pragma unroll
                    for (int j = 0; j < JN; ++j){
                        const uint32_t bx = bb[j>>1][j&1], by = bb[j>>1][(j&1)+2];
                        MMA(accU[0][j], a0[0],a0[1],a0[2],a0[3], bx, by);
                        MMA(accU[1][j], a1[0],a1[1],a1[2],a1[3], bx, by);
                    }
                }
            }
        }
    }

    // ---------------- epilogue ----------------
    #pragma unroll
    for (int m = 0; m < 2; ++m){
        #pragma unroll
        for (int j = 0; j < JN; ++j){
            const int r0 = m0 + wm*32 + m*16 + (lane >> 2);
            const int c0 = n0 + wn*WTN + j*8 + (lane & 3)*2;
            if constexpr (DUAL){
                h16* gh = (h16*)g_h_;
                float hv[4];
                #pragma unroll
                for (int q = 0; q < 4; ++q){
                    const float g = accG[m][j][q], u = accU[m][j][q];
                    hv[q] = g * u / (1.f + __expf(-g));
                }
                *(__half2*)(gh + (size_t)r0*MWIDTH + c0)     = __floats2half2_rn(hv[0], hv[1]);
                *(__half2*)(gh + (size_t)(r0+8)*MWIDTH + c0) = __floats2half2_rn(hv[2], hv[3]);
            } else {
                *(float2*)(OutP + (size_t)r0*DMODEL + c0)
                    = make_float2(accG[m][j][0], accG[m][j][1]);
                *(float2*)(OutP + (size_t)(r0+8)*DMODEL + c0)
                    = make_float2(accG[m][j][2], accG[m][j][3]);
            }
        }
    }
}

// ---------------------------------------------------------------------------
extern "C" void kernel_launch(void* const* d_in, const int* in_sizes, int n_in,
                              void* d_out, int out_size)
{
    const float* x  = (const float*)d_in[0];
    const float* Wr = (const float*)d_in[1];
    const float* br = (const float*)d_in[2];
    const float* Wg = (const float*)d_in[3];
    const float* Wu = (const float*)d_in[4];
    const float* Wd = (const float*)d_in[5];
    const float* Ag = (const float*)d_in[6];
    const float* Au = (const float*)d_in[7];
    const float* Ad = (const float*)d_in[8];
    const float* Bg = (const float*)d_in[9];
    const float* Bu = (const float*)d_in[10];
    const float* Bd = (const float*)d_in[11];

    float* out     = (float*)d_out;
    float* routing = out + (size_t)NTOK * DMODEL;
    float* choice  = routing + NTOK * NEXP;

    void *xp,*wg,*wu,*wd,*bg,*bu,*bd;
    cudaGetSymbolAddress(&xp, g_x_);
    cudaGetSymbolAddress(&wg, g_wg_); cudaGetSymbolAddress(&wu, g_wu_);
    cudaGetSymbolAddress(&wd, g_wd_);
    cudaGetSymbolAddress(&bg, g_bg_); cudaGetSymbolAddress(&bu, g_bu_);
    cudaGetSymbolAddress(&bd, g_bd_);

    const int n4x = NTOK*DMODEL/4, n4w = MWIDTH*DMODEL/4;
    // all fp32->fp16 conversions in one launch (y: 0=x, 1..3=weights)
    k_cvt<<<dim3((n4w+255)/256, 4), 256>>>(x, (h16*)xp, n4x,
                                           Wg, (h16*)wg, Wu, (h16*)wu, Wd, (h16*)wd, n4w);
    // all three B flattens in one launch (y: 0=Bg, 1=Bu, 2=Bd)
    k_bflat<<<dim3(MWIDTH, 3), 128>>>(Bg, (h16*)bg, Bu, (h16*)bu, Bd, (h16*)bd);

    k_router<<<NTOK, 256>>>(x, Wr, br, Ag, Au, routing, choice);

    const int smem_sz = 3 * 32768;   // 98304 both variants
    cudaFuncSetAttribute(k_mma<true>,  cudaFuncAttributeMaxDynamicSharedMemorySize, smem_sz);
    cudaFuncSetAttribute(k_mma<false>, cudaFuncAttributeMaxDynamicSharedMemorySize, smem_sz);

    // DUAL: grid (m-blocks=32, n-blocks=88) — concurrent CTAs share B in L2
    k_mma<true><<<dim3(NTOK/128, MWIDTH/64), 256, smem_sz>>>(nullptr);
    k_hd<<<NTOK, 256>>>(Ad, routing);
    // down: grid (n-blocks=16, m-blocks=32)
    k_mma<false><<<dim3(DMODEL/128, NTOK/128), 256, smem_sz>>>(out);
}